// round 1
// baseline (speedup 1.0000x reference)
#include <cuda_runtime.h>
#include <cstdio>

#define V_WORDS 50000
#define HD 128
#define N_DOCS 20000

// Scratch (allocation-free rule: __device__ globals)
__device__ float g_buf1[V_WORDS * HD];   // 25.6 MB
__device__ float g_buf2[V_WORDS * HD];   // 25.6 MB
__device__ float g_doc[N_DOCS * HD];     // 10.24 MB

// ---------------------------------------------------------------------------
// zero fill (float4-wide)
// ---------------------------------------------------------------------------
__global__ void k_fill_zero(float4* __restrict__ p, int n4) {
    int i = blockIdx.x * blockDim.x + threadIdx.x;
    if (i < n4) p[i] = make_float4(0.f, 0.f, 0.f, 0.f);
}

// ---------------------------------------------------------------------------
// SpMM: out[row[e], :] += val[e] * dense[col[e], :]   (one warp per edge)
// out must be pre-zeroed. Uses vector red.global.add.v4.f32 (sm_90+).
// ---------------------------------------------------------------------------
__global__ void k_spmm(const int* __restrict__ row, const int* __restrict__ col,
                       const float* __restrict__ val, const float* __restrict__ dense,
                       float* __restrict__ out, int nnz) {
    int t = blockIdx.x * blockDim.x + threadIdx.x;
    int e = t >> 5;
    if (e >= nnz) return;
    int lane = t & 31;
    int r = __ldg(row + e);
    int c = __ldg(col + e);
    float v = __ldg(val + e);

    const float4* src = reinterpret_cast<const float4*>(dense + (size_t)c * HD);
    float4 x = __ldg(src + lane);
    float4 y = make_float4(v * x.x, v * x.y, v * x.z, v * x.w);

    float* dst = out + (size_t)r * HD + lane * 4;
    asm volatile("red.global.add.v4.f32 [%0], {%1, %2, %3, %4};"
                 :: "l"(dst), "f"(y.x), "f"(y.y), "f"(y.z), "f"(y.w)
                 : "memory");
}

// ---------------------------------------------------------------------------
// out = relu(X @ W^T), X:[R,128], W:[128,128] row-major (out[i][j]=sum_k X[i][k]*W[j][k])
// 64 rows per block, 256 threads, 4x8 register micro-tile, W+X in dynamic smem.
// ---------------------------------------------------------------------------
#define GEMM_BR 64
#define GEMM_PAD 129
__global__ void k_gemm_relu(const float* __restrict__ X, const float* __restrict__ W,
                            float* __restrict__ out, int R) {
    extern __shared__ float sm[];
    float* Ws = sm;                       // [128][129]
    float* Xs = sm + 128 * GEMM_PAD;      // [64][129]
    int tid = threadIdx.x;

    for (int i = tid; i < 128 * 128; i += 256) {
        int c = i >> 7, k = i & 127;
        Ws[c * GEMM_PAD + k] = W[i];
    }
    int rb = blockIdx.x * GEMM_BR;
    for (int i = tid; i < GEMM_BR * 128; i += 256) {
        int r = i >> 7, k = i & 127;
        int gr = rb + r;
        Xs[r * GEMM_PAD + k] = (gr < R) ? X[(size_t)gr * HD + k] : 0.f;
    }
    __syncthreads();

    int tx = tid & 15, ty = tid >> 4;
    int r0 = ty * 4;          // 16*4 = 64 rows
    int c0 = tx * 8;          // 16*8 = 128 cols
    float acc[4][8];
    #pragma unroll
    for (int i = 0; i < 4; i++)
        #pragma unroll
        for (int j = 0; j < 8; j++) acc[i][j] = 0.f;

    #pragma unroll 4
    for (int k = 0; k < 128; k++) {
        float xv[4], wv[8];
        #pragma unroll
        for (int i = 0; i < 4; i++) xv[i] = Xs[(r0 + i) * GEMM_PAD + k];
        #pragma unroll
        for (int j = 0; j < 8; j++) wv[j] = Ws[(c0 + j) * GEMM_PAD + k];
        #pragma unroll
        for (int i = 0; i < 4; i++)
            #pragma unroll
            for (int j = 0; j < 8; j++) acc[i][j] += xv[i] * wv[j];
    }

    #pragma unroll
    for (int i = 0; i < 4; i++) {
        int gr = rb + r0 + i;
        if (gr < R) {
            #pragma unroll
            for (int j = 0; j < 8; j++)
                out[(size_t)gr * HD + c0 + j] = fmaxf(acc[i][j], 0.f);
        }
    }
}

// ---------------------------------------------------------------------------
// S = layernorm(0.3*emb + 0.7*hx) * g + b + emb     (one warp per row)
// ---------------------------------------------------------------------------
__global__ void k_resid_ln_addemb(const float* __restrict__ hx, const float* __restrict__ emb,
                                  const float* __restrict__ g, const float* __restrict__ b,
                                  float* __restrict__ out) {
    int w = (blockIdx.x * blockDim.x + threadIdx.x) >> 5;
    int lane = threadIdx.x & 31;
    if (w >= V_WORDS) return;

    float4 h = __ldg(reinterpret_cast<const float4*>(hx + (size_t)w * HD) + lane);
    float4 e = __ldg(reinterpret_cast<const float4*>(emb + (size_t)w * HD) + lane);
    const float a = 0.7f, oma = 1.0f - 0.7f;
    float4 x;
    x.x = oma * e.x + a * h.x;
    x.y = oma * e.y + a * h.y;
    x.z = oma * e.z + a * h.z;
    x.w = oma * e.w + a * h.w;

    float s  = x.x + x.y + x.z + x.w;
    float sq = x.x * x.x + x.y * x.y + x.z * x.z + x.w * x.w;
    #pragma unroll
    for (int o = 16; o; o >>= 1) {
        s  += __shfl_xor_sync(0xFFFFFFFFu, s, o);
        sq += __shfl_xor_sync(0xFFFFFFFFu, sq, o);
    }
    float mu  = s * (1.0f / 128.0f);
    float var = sq * (1.0f / 128.0f) - mu * mu;
    float inv = rsqrtf(var + 1e-5f);

    float4 gv = __ldg(reinterpret_cast<const float4*>(g) + lane);
    float4 bv = __ldg(reinterpret_cast<const float4*>(b) + lane);
    float4 o;
    o.x = (x.x - mu) * inv * gv.x + bv.x + e.x;
    o.y = (x.y - mu) * inv * gv.y + bv.y + e.y;
    o.z = (x.z - mu) * inv * gv.z + bv.z + e.z;
    o.w = (x.w - mu) * inv * gv.w + bv.w + e.w;
    reinterpret_cast<float4*>(out + (size_t)w * HD)[lane] = o;
}

// ---------------------------------------------------------------------------
// head: logits = relu(doc @ mlpW^T + mlpb) @ clfW^T + clfb    (128 thr/block)
// ---------------------------------------------------------------------------
__global__ void k_head(const float* __restrict__ doc, const float* __restrict__ mlpW,
                       const float* __restrict__ mlpb, const float* __restrict__ clfW,
                       const float* __restrict__ clfb, float* __restrict__ out) {
    extern __shared__ float sm[];
    float* Ws = sm;                       // [128][129]
    float* xs = Ws + 128 * GEMM_PAD;      // [128]
    float* mb = xs + 128;                 // [128]
    float* c0 = mb + 128;                 // [128]
    float* c1 = c0 + 128;                 // [128]
    __shared__ float red0[4], red1[4];

    int tid = threadIdx.x;
    for (int i = tid; i < 128 * 128; i += 128) {
        int r = i >> 7, k = i & 127;
        Ws[r * GEMM_PAD + k] = mlpW[i];
    }
    mb[tid] = mlpb[tid];
    c0[tid] = clfW[tid];
    c1[tid] = clfW[128 + tid];
    float cb0 = clfb[0], cb1 = clfb[1];
    __syncthreads();

    int lane = tid & 31, wid = tid >> 5;
    for (int d = blockIdx.x; d < N_DOCS; d += gridDim.x) {
        xs[tid] = doc[(size_t)d * HD + tid];
        __syncthreads();
        float acc = mb[tid];
        #pragma unroll 8
        for (int k = 0; k < 128; k++)
            acc += xs[k] * Ws[tid * GEMM_PAD + k];
        float h = fmaxf(acc, 0.f);
        float p0 = h * c0[tid];
        float p1 = h * c1[tid];
        #pragma unroll
        for (int o = 16; o; o >>= 1) {
            p0 += __shfl_down_sync(0xFFFFFFFFu, p0, o);
            p1 += __shfl_down_sync(0xFFFFFFFFu, p1, o);
        }
        if (lane == 0) { red0[wid] = p0; red1[wid] = p1; }
        __syncthreads();
        if (tid == 0) out[(size_t)d * 2]     = red0[0] + red0[1] + red0[2] + red0[3] + cb0;
        if (tid == 1) out[(size_t)d * 2 + 1] = red1[0] + red1[1] + red1[2] + red1[3] + cb1;
        __syncthreads();
    }
}

// ---------------------------------------------------------------------------
extern "C" void kernel_launch(void* const* d_in, const int* in_sizes, int n_in,
                              void* d_out, int out_size) {
    const int*   A_row  = (const int*)  d_in[0];
    const int*   A_col  = (const int*)  d_in[1];
    const float* A_val  = (const float*)d_in[2];
    const int*   X_row  = (const int*)  d_in[3];
    const int*   X_col  = (const int*)  d_in[4];
    const float* X_val  = (const float*)d_in[5];
    const float* emb_W  = (const float*)d_in[6];
    const float* lin1_W = (const float*)d_in[7];
    const float* lin2_W = (const float*)d_in[8];
    const float* norm_g = (const float*)d_in[9];
    const float* norm_b = (const float*)d_in[10];
    const float* mlp_W  = (const float*)d_in[11];
    const float* mlp_b  = (const float*)d_in[12];
    const float* clf_W  = (const float*)d_in[13];
    const float* clf_b  = (const float*)d_in[14];
    float* out = (float*)d_out;

    int E   = in_sizes[0];
    int NNZ = in_sizes[3];

    void *pb1, *pb2, *pdoc;
    cudaGetSymbolAddress(&pb1, g_buf1);
    cudaGetSymbolAddress(&pb2, g_buf2);
    cudaGetSymbolAddress(&pdoc, g_doc);
    float* b1 = (float*)pb1;
    float* b2 = (float*)pb2;
    float* bd = (float*)pdoc;

    const int gemm_smem = (128 * GEMM_PAD + GEMM_BR * GEMM_PAD) * sizeof(float);  // ~99 KB
    const int head_smem = (128 * GEMM_PAD + 4 * 128) * sizeof(float);             // ~68 KB
    cudaFuncSetAttribute(k_gemm_relu, cudaFuncAttributeMaxDynamicSharedMemorySize, gemm_smem);
    cudaFuncSetAttribute(k_head,      cudaFuncAttributeMaxDynamicSharedMemorySize, head_smem);

    const int n4_word = V_WORDS * HD / 4;
    const int n4_doc  = N_DOCS * HD / 4;
    const int fill_grid_w = (n4_word + 255) / 256;
    const int fill_grid_d = (n4_doc + 255) / 256;
    const int spmm_grid_A = (E * 32 + 255) / 256;
    const int spmm_grid_X = (NNZ * 32 + 255) / 256;
    const int gemm_grid   = (V_WORDS + GEMM_BR - 1) / GEMM_BR;
    const int ln_grid     = (V_WORDS * 32 + 255) / 256;

    // 1) T1 = A @ emb_W
    k_fill_zero<<<fill_grid_w, 256>>>((float4*)b1, n4_word);
    k_spmm<<<spmm_grid_A, 256>>>(A_row, A_col, A_val, emb_W, b1, E);
    // 2) T2 = relu(T1 @ lin1^T)
    k_gemm_relu<<<gemm_grid, 256, gemm_smem>>>(b1, lin1_W, b2, V_WORDS);
    // 3) T1 = A @ T2
    k_fill_zero<<<fill_grid_w, 256>>>((float4*)b1, n4_word);
    k_spmm<<<spmm_grid_A, 256>>>(A_row, A_col, A_val, b2, b1, E);
    // 4) T2 = relu(T1 @ lin2^T)
    k_gemm_relu<<<gemm_grid, 256, gemm_smem>>>(b1, lin2_W, b2, V_WORDS);
    // 5) b1 = LN(0.3*emb + 0.7*T2)*g + b + emb   (= word_H + emb_W, fused doc-pool operand)
    k_resid_ln_addemb<<<ln_grid, 256>>>(b2, emb_W, norm_g, norm_b, b1);
    // 6) doc = X @ b1   (covers both X@word_H and X@emb_W by linearity)
    k_fill_zero<<<fill_grid_d, 256>>>((float4*)bd, n4_doc);
    k_spmm<<<spmm_grid_X, 256>>>(X_row, X_col, X_val, b1, bd, NNZ);
    // 7) logits
    k_head<<<2000, 128, head_smem>>>(bd, mlp_W, mlp_b, clf_W, clf_b, out);
}

// round 2
// speedup vs baseline: 1.2711x; 1.2711x over previous
#include <cuda_runtime.h>

#define V_WORDS 50000
#define HD 128
#define N_DOCS 20000
#define E_CAP 1600000

// Scratch (allocation-free rule: __device__ globals)
__device__ float g_buf1[V_WORDS * HD];   // 25.6 MB
__device__ float g_buf2[V_WORDS * HD];   // 25.6 MB
__device__ float g_doc[N_DOCS * HD];     // 10.24 MB
__device__ int2  g_Aed[E_CAP];           // sorted (col, val-bits) for A
__device__ int2  g_Xed[E_CAP];           // sorted (col, val-bits) for X
__device__ int   g_Arp[V_WORDS + 1];
__device__ int   g_Awp[V_WORDS];
__device__ int   g_Acnt[V_WORDS];
__device__ int   g_Xrp[N_DOCS + 1];
__device__ int   g_Xwp[N_DOCS];
__device__ int   g_Xcnt[N_DOCS];

// ---------------------------------------------------------------------------
__global__ void k_zero_int(int* __restrict__ p, int n) {
    int i = blockIdx.x * blockDim.x + threadIdx.x;
    if (i < n) p[i] = 0;
}

__global__ void k_hist(const int* __restrict__ row, int* __restrict__ cnt, int nnz) {
    int e = blockIdx.x * blockDim.x + threadIdx.x;
    if (e < nnz) atomicAdd(cnt + __ldg(row + e), 1);
}

// single-block exclusive scan (n <= 1024 * chunk)
__global__ void k_scan(const int* __restrict__ cnt, int* __restrict__ rp,
                       int* __restrict__ wp, int n) {
    __shared__ int part[1024];
    int tid = threadIdx.x;
    int chunk = (n + 1023) >> 10;
    int beg = tid * chunk;
    int end = min(beg + chunk, n);
    int s = 0;
    for (int i = beg; i < end; i++) s += cnt[i];
    part[tid] = s;
    __syncthreads();
    for (int off = 1; off < 1024; off <<= 1) {
        int v = (tid >= off) ? part[tid - off] : 0;
        __syncthreads();
        part[tid] += v;
        __syncthreads();
    }
    int run = (tid == 0) ? 0 : part[tid - 1];
    for (int i = beg; i < end; i++) {
        int c = cnt[i];
        rp[i] = run;
        wp[i] = run;
        run += c;
    }
    if (tid == 1023) rp[n] = part[1023];
}

__global__ void k_scatter(const int* __restrict__ row, const int* __restrict__ col,
                          const float* __restrict__ val, int* __restrict__ wp,
                          int2* __restrict__ ed, int nnz) {
    int e = blockIdx.x * blockDim.x + threadIdx.x;
    if (e >= nnz) return;
    int r = __ldg(row + e);
    int p = atomicAdd(wp + r, 1);
    ed[p] = make_int2(__ldg(col + e), __float_as_int(__ldg(val + e)));
}

// ---------------------------------------------------------------------------
// CSR SpMM: one warp per output row, segmented reduction in registers.
// No atomics, no pre-zeroing. Edge metadata broadcast via shfl.
// ---------------------------------------------------------------------------
__global__ void k_spmm_csr(const int* __restrict__ rp, const int2* __restrict__ ed,
                           const float* __restrict__ dense, float* __restrict__ out,
                           int nrows) {
    int wrow = (blockIdx.x * blockDim.x + threadIdx.x) >> 5;
    if (wrow >= nrows) return;
    int lane = threadIdx.x & 31;
    int start = __ldg(rp + wrow);
    int end   = __ldg(rp + wrow + 1);

    const float4* d4 = reinterpret_cast<const float4*>(dense);
    float4 acc = make_float4(0.f, 0.f, 0.f, 0.f);

    for (int base = start; base < end; base += 32) {
        int idx = base + lane;
        int2 e = (idx < end) ? __ldg(ed + idx) : make_int2(0, 0);  // v=0 pad -> no-op
        #pragma unroll
        for (int j = 0; j < 32; j++) {
            int   c = __shfl_sync(0xFFFFFFFFu, e.x, j);
            float v = __int_as_float(__shfl_sync(0xFFFFFFFFu, e.y, j));
            float4 x = __ldg(d4 + (size_t)c * 32 + lane);
            acc.x = fmaf(v, x.x, acc.x);
            acc.y = fmaf(v, x.y, acc.y);
            acc.z = fmaf(v, x.z, acc.z);
            acc.w = fmaf(v, x.w, acc.w);
        }
    }
    reinterpret_cast<float4*>(out)[(size_t)wrow * 32 + lane] = acc;
}

// ---------------------------------------------------------------------------
// out = relu(X @ W^T), X:[R,128], W:[128,128] row-major
// ---------------------------------------------------------------------------
#define GEMM_BR 64
#define GEMM_PAD 129
__global__ void k_gemm_relu(const float* __restrict__ X, const float* __restrict__ W,
                            float* __restrict__ out, int R) {
    extern __shared__ float sm[];
    float* Ws = sm;                       // [128][129]
    float* Xs = sm + 128 * GEMM_PAD;      // [64][129]
    int tid = threadIdx.x;

    for (int i = tid; i < 128 * 128; i += 256) {
        int c = i >> 7, k = i & 127;
        Ws[c * GEMM_PAD + k] = W[i];
    }
    int rb = blockIdx.x * GEMM_BR;
    for (int i = tid; i < GEMM_BR * 128; i += 256) {
        int r = i >> 7, k = i & 127;
        int gr = rb + r;
        Xs[r * GEMM_PAD + k] = (gr < R) ? X[(size_t)gr * HD + k] : 0.f;
    }
    __syncthreads();

    int tx = tid & 15, ty = tid >> 4;
    int r0 = ty * 4;
    int c0 = tx * 8;
    float acc[4][8];
    #pragma unroll
    for (int i = 0; i < 4; i++)
        #pragma unroll
        for (int j = 0; j < 8; j++) acc[i][j] = 0.f;

    #pragma unroll 4
    for (int k = 0; k < 128; k++) {
        float xv[4], wv[8];
        #pragma unroll
        for (int i = 0; i < 4; i++) xv[i] = Xs[(r0 + i) * GEMM_PAD + k];
        #pragma unroll
        for (int j = 0; j < 8; j++) wv[j] = Ws[(c0 + j) * GEMM_PAD + k];
        #pragma unroll
        for (int i = 0; i < 4; i++)
            #pragma unroll
            for (int j = 0; j < 8; j++) acc[i][j] += xv[i] * wv[j];
    }

    #pragma unroll
    for (int i = 0; i < 4; i++) {
        int gr = rb + r0 + i;
        if (gr < R) {
            #pragma unroll
            for (int j = 0; j < 8; j++)
                out[(size_t)gr * HD + c0 + j] = fmaxf(acc[i][j], 0.f);
        }
    }
}

// ---------------------------------------------------------------------------
// S = layernorm(0.3*emb + 0.7*hx) * g + b + emb     (one warp per row)
// ---------------------------------------------------------------------------
__global__ void k_resid_ln_addemb(const float* __restrict__ hx, const float* __restrict__ emb,
                                  const float* __restrict__ g, const float* __restrict__ b,
                                  float* __restrict__ out) {
    int w = (blockIdx.x * blockDim.x + threadIdx.x) >> 5;
    int lane = threadIdx.x & 31;
    if (w >= V_WORDS) return;

    float4 h = __ldg(reinterpret_cast<const float4*>(hx + (size_t)w * HD) + lane);
    float4 e = __ldg(reinterpret_cast<const float4*>(emb + (size_t)w * HD) + lane);
    const float a = 0.7f, oma = 1.0f - 0.7f;
    float4 x;
    x.x = oma * e.x + a * h.x;
    x.y = oma * e.y + a * h.y;
    x.z = oma * e.z + a * h.z;
    x.w = oma * e.w + a * h.w;

    float s  = x.x + x.y + x.z + x.w;
    float sq = x.x * x.x + x.y * x.y + x.z * x.z + x.w * x.w;
    #pragma unroll
    for (int o = 16; o; o >>= 1) {
        s  += __shfl_xor_sync(0xFFFFFFFFu, s, o);
        sq += __shfl_xor_sync(0xFFFFFFFFu, sq, o);
    }
    float mu  = s * (1.0f / 128.0f);
    float var = sq * (1.0f / 128.0f) - mu * mu;
    float inv = rsqrtf(var + 1e-5f);

    float4 gv = __ldg(reinterpret_cast<const float4*>(g) + lane);
    float4 bv = __ldg(reinterpret_cast<const float4*>(b) + lane);
    float4 o;
    o.x = (x.x - mu) * inv * gv.x + bv.x + e.x;
    o.y = (x.y - mu) * inv * gv.y + bv.y + e.y;
    o.z = (x.z - mu) * inv * gv.z + bv.z + e.z;
    o.w = (x.w - mu) * inv * gv.w + bv.w + e.w;
    reinterpret_cast<float4*>(out + (size_t)w * HD)[lane] = o;
}

// ---------------------------------------------------------------------------
// head: logits = relu(doc @ mlpW^T + mlpb) @ clfW^T + clfb
// ---------------------------------------------------------------------------
__global__ void k_head(const float* __restrict__ doc, const float* __restrict__ mlpW,
                       const float* __restrict__ mlpb, const float* __restrict__ clfW,
                       const float* __restrict__ clfb, float* __restrict__ out) {
    extern __shared__ float sm[];
    float* Ws = sm;                       // [128][129]
    float* xs = Ws + 128 * GEMM_PAD;      // [128]
    float* mb = xs + 128;                 // [128]
    float* c0 = mb + 128;                 // [128]
    float* c1 = c0 + 128;                 // [128]
    __shared__ float red0[4], red1[4];

    int tid = threadIdx.x;
    for (int i = tid; i < 128 * 128; i += 128) {
        int r = i >> 7, k = i & 127;
        Ws[r * GEMM_PAD + k] = mlpW[i];
    }
    mb[tid] = mlpb[tid];
    c0[tid] = clfW[tid];
    c1[tid] = clfW[128 + tid];
    float cb0 = clfb[0], cb1 = clfb[1];
    __syncthreads();

    int lane = tid & 31, wid = tid >> 5;
    for (int d = blockIdx.x; d < N_DOCS; d += gridDim.x) {
        xs[tid] = doc[(size_t)d * HD + tid];
        __syncthreads();
        float acc = mb[tid];
        #pragma unroll 8
        for (int k = 0; k < 128; k++)
            acc += xs[k] * Ws[tid * GEMM_PAD + k];
        float h = fmaxf(acc, 0.f);
        float p0 = h * c0[tid];
        float p1 = h * c1[tid];
        #pragma unroll
        for (int o = 16; o; o >>= 1) {
            p0 += __shfl_down_sync(0xFFFFFFFFu, p0, o);
            p1 += __shfl_down_sync(0xFFFFFFFFu, p1, o);
        }
        if (lane == 0) { red0[wid] = p0; red1[wid] = p1; }
        __syncthreads();
        if (tid == 0) out[(size_t)d * 2]     = red0[0] + red0[1] + red0[2] + red0[3] + cb0;
        if (tid == 1) out[(size_t)d * 2 + 1] = red1[0] + red1[1] + red1[2] + red1[3] + cb1;
        __syncthreads();
    }
}

// ---------------------------------------------------------------------------
extern "C" void kernel_launch(void* const* d_in, const int* in_sizes, int n_in,
                              void* d_out, int out_size) {
    const int*   A_row  = (const int*)  d_in[0];
    const int*   A_col  = (const int*)  d_in[1];
    const float* A_val  = (const float*)d_in[2];
    const int*   X_row  = (const int*)  d_in[3];
    const int*   X_col  = (const int*)  d_in[4];
    const float* X_val  = (const float*)d_in[5];
    const float* emb_W  = (const float*)d_in[6];
    const float* lin1_W = (const float*)d_in[7];
    const float* lin2_W = (const float*)d_in[8];
    const float* norm_g = (const float*)d_in[9];
    const float* norm_b = (const float*)d_in[10];
    const float* mlp_W  = (const float*)d_in[11];
    const float* mlp_b  = (const float*)d_in[12];
    const float* clf_W  = (const float*)d_in[13];
    const float* clf_b  = (const float*)d_in[14];
    float* out = (float*)d_out;

    int E   = in_sizes[0];
    int NNZ = in_sizes[3];

    void *pb1, *pb2, *pdoc, *pAed, *pXed, *pArp, *pAwp, *pAcnt, *pXrp, *pXwp, *pXcnt;
    cudaGetSymbolAddress(&pb1, g_buf1);
    cudaGetSymbolAddress(&pb2, g_buf2);
    cudaGetSymbolAddress(&pdoc, g_doc);
    cudaGetSymbolAddress(&pAed, g_Aed);
    cudaGetSymbolAddress(&pXed, g_Xed);
    cudaGetSymbolAddress(&pArp, g_Arp);
    cudaGetSymbolAddress(&pAwp, g_Awp);
    cudaGetSymbolAddress(&pAcnt, g_Acnt);
    cudaGetSymbolAddress(&pXrp, g_Xrp);
    cudaGetSymbolAddress(&pXwp, g_Xwp);
    cudaGetSymbolAddress(&pXcnt, g_Xcnt);
    float* b1 = (float*)pb1;
    float* b2 = (float*)pb2;
    float* bd = (float*)pdoc;
    int2* Aed = (int2*)pAed;
    int2* Xed = (int2*)pXed;
    int *Arp = (int*)pArp, *Awp = (int*)pAwp, *Acnt = (int*)pAcnt;
    int *Xrp = (int*)pXrp, *Xwp = (int*)pXwp, *Xcnt = (int*)pXcnt;

    const int gemm_smem = (128 * GEMM_PAD + GEMM_BR * GEMM_PAD) * sizeof(float);
    const int head_smem = (128 * GEMM_PAD + 4 * 128) * sizeof(float);
    cudaFuncSetAttribute(k_gemm_relu, cudaFuncAttributeMaxDynamicSharedMemorySize, gemm_smem);
    cudaFuncSetAttribute(k_head,      cudaFuncAttributeMaxDynamicSharedMemorySize, head_smem);

    const int eg   = (E + 255) / 256;
    const int xg   = (NNZ + 255) / 256;
    const int spmmA_grid = (V_WORDS * 32 + 255) / 256;
    const int spmmX_grid = (N_DOCS * 32 + 255) / 256;
    const int gemm_grid  = (V_WORDS + GEMM_BR - 1) / GEMM_BR;
    const int ln_grid    = (V_WORDS * 32 + 255) / 256;

    // --- Build CSR for A (used twice) ---
    k_zero_int<<<(V_WORDS + 255) / 256, 256>>>(Acnt, V_WORDS);
    k_hist<<<eg, 256>>>(A_row, Acnt, E);
    k_scan<<<1, 1024>>>(Acnt, Arp, Awp, V_WORDS);
    k_scatter<<<eg, 256>>>(A_row, A_col, A_val, Awp, Aed, E);

    // --- Build CSR for X ---
    k_zero_int<<<(N_DOCS + 255) / 256, 256>>>(Xcnt, N_DOCS);
    k_hist<<<xg, 256>>>(X_row, Xcnt, NNZ);
    k_scan<<<1, 1024>>>(Xcnt, Xrp, Xwp, N_DOCS);
    k_scatter<<<xg, 256>>>(X_row, X_col, X_val, Xwp, Xed, NNZ);

    // 1) b1 = A @ emb_W
    k_spmm_csr<<<spmmA_grid, 256>>>(Arp, Aed, emb_W, b1, V_WORDS);
    // 2) b2 = relu(b1 @ lin1^T)
    k_gemm_relu<<<gemm_grid, 256, gemm_smem>>>(b1, lin1_W, b2, V_WORDS);
    // 3) b1 = A @ b2
    k_spmm_csr<<<spmmA_grid, 256>>>(Arp, Aed, b2, b1, V_WORDS);
    // 4) b2 = relu(b1 @ lin2^T)
    k_gemm_relu<<<gemm_grid, 256, gemm_smem>>>(b1, lin2_W, b2, V_WORDS);
    // 5) b1 = LN(0.3*emb + 0.7*b2)*g + b + emb   (fused doc-pool operand)
    k_resid_ln_addemb<<<ln_grid, 256>>>(b2, emb_W, norm_g, norm_b, b1);
    // 6) doc = X @ b1
    k_spmm_csr<<<spmmX_grid, 256>>>(Xrp, Xed, b1, bd, N_DOCS);
    // 7) logits
    k_head<<<2000, 128, head_smem>>>(bd, mlp_W, mlp_b, clf_W, clf_b, out);
}

// round 3
// speedup vs baseline: 1.3850x; 1.0896x over previous
#include <cuda_runtime.h>

#define V_WORDS 50000
#define HD 128
#define N_DOCS 20000
#define E_CAP 1600000

typedef unsigned long long ull;

#define FFMA2(d, a, b, c) \
    asm("fma.rn.f32x2 %0, %1, %2, %3;" : "=l"(d) : "l"(a), "l"(b), "l"(c))
#define PACK2(d, f) \
    asm("mov.b64 %0, {%1, %1};" : "=l"(d) : "f"(f))
#define UNPACK2(lo, hi, v) \
    asm("mov.b64 {%0, %1}, %2;" : "=f"(lo), "=f"(hi) : "l"(v))

// Scratch (allocation-free rule: __device__ globals)
__device__ float g_buf1[V_WORDS * HD];
__device__ float g_buf2[V_WORDS * HD];
__device__ float g_doc[N_DOCS * HD];
__device__ int2  g_Aed[E_CAP];
__device__ int2  g_Xed[E_CAP];
__device__ int   g_Arp[V_WORDS + 1];
__device__ int   g_Awp[V_WORDS];
__device__ int   g_Acnt[V_WORDS];
__device__ int   g_Xrp[N_DOCS + 1];
__device__ int   g_Xwp[N_DOCS];
__device__ int   g_Xcnt[N_DOCS];

// ---------------------------------------------------------------------------
__global__ void k_zero_int(int* __restrict__ p, int n) {
    int i = blockIdx.x * blockDim.x + threadIdx.x;
    if (i < n) p[i] = 0;
}

__global__ void k_hist(const int* __restrict__ row, int* __restrict__ cnt, int nnz) {
    int e = blockIdx.x * blockDim.x + threadIdx.x;
    if (e < nnz) atomicAdd(cnt + __ldg(row + e), 1);
}

// single-block exclusive scan
__global__ void k_scan(const int* __restrict__ cnt, int* __restrict__ rp,
                       int* __restrict__ wp, int n) {
    __shared__ int part[1024];
    int tid = threadIdx.x;
    int chunk = (n + 1023) >> 10;
    int beg = tid * chunk;
    int end = min(beg + chunk, n);
    int s = 0;
    for (int i = beg; i < end; i++) s += cnt[i];
    part[tid] = s;
    __syncthreads();
    for (int off = 1; off < 1024; off <<= 1) {
        int v = (tid >= off) ? part[tid - off] : 0;
        __syncthreads();
        part[tid] += v;
        __syncthreads();
    }
    int run = (tid == 0) ? 0 : part[tid - 1];
    for (int i = beg; i < end; i++) {
        int c = cnt[i];
        rp[i] = run;
        wp[i] = run;
        run += c;
    }
    if (tid == 1023) rp[n] = part[1023];
}

__global__ void k_scatter(const int* __restrict__ row, const int* __restrict__ col,
                          const float* __restrict__ val, int* __restrict__ wp,
                          int2* __restrict__ ed, int nnz) {
    int e = blockIdx.x * blockDim.x + threadIdx.x;
    if (e >= nnz) return;
    int r = __ldg(row + e);
    int p = atomicAdd(wp + r, 1);
    ed[p] = make_int2(__ldg(col + e), __float_as_int(__ldg(val + e)));
}

// ---------------------------------------------------------------------------
// CSR SpMM: one warp per output row, exact chunk trip counts (no pad gathers)
// ---------------------------------------------------------------------------
#define SPMM_BODY(j)                                                        \
    {                                                                       \
        int   c = __shfl_sync(0xFFFFFFFFu, e.x, (j));                       \
        float v = __int_as_float(__shfl_sync(0xFFFFFFFFu, e.y, (j)));       \
        float4 x = __ldg(d4 + (size_t)c * 32 + lane);                       \
        acc.x = fmaf(v, x.x, acc.x);                                        \
        acc.y = fmaf(v, x.y, acc.y);                                        \
        acc.z = fmaf(v, x.z, acc.z);                                        \
        acc.w = fmaf(v, x.w, acc.w);                                        \
    }

__global__ void k_spmm_csr(const int* __restrict__ rp, const int2* __restrict__ ed,
                           const float* __restrict__ dense, float* __restrict__ out,
                           int nrows) {
    int wrow = (blockIdx.x * blockDim.x + threadIdx.x) >> 5;
    if (wrow >= nrows) return;
    int lane = threadIdx.x & 31;
    int start = __ldg(rp + wrow);
    int end   = __ldg(rp + wrow + 1);

    const float4* d4 = reinterpret_cast<const float4*>(dense);
    float4 acc = make_float4(0.f, 0.f, 0.f, 0.f);

    for (int base = start; base < end; base += 32) {
        int idx = base + lane;
        int2 e = (idx < end) ? __ldg(ed + idx) : make_int2(0, 0);
        int cnt = end - base;
        if (cnt >= 32) {
            #pragma unroll
            for (int j = 0; j < 32; j++) SPMM_BODY(j)
        } else {
            for (int j = 0; j < cnt; j++) SPMM_BODY(j)
        }
    }
    reinterpret_cast<float4*>(out)[(size_t)wrow * 32 + lane] = acc;
}

// ---------------------------------------------------------------------------
// Fused GEMM: out = relu(X @ W^T) [do_ln=0]
//   or       out = LN(0.3*emb + 0.7*relu(X @ W^T))*g + b + emb [do_ln=1]
// f32x2 packed math, 64-row tiles, W k-major in smem.
// ---------------------------------------------------------------------------
#define GEMM_BR 64
#define WPAD 130
#define XPAD 129

__global__ void k_gemm_fused(const float* __restrict__ X, const float* __restrict__ W,
                             float* __restrict__ out, int R, int do_ln,
                             const float* __restrict__ emb, const float* __restrict__ gw,
                             const float* __restrict__ bw) {
    extern __shared__ float sm[];
    float* Wt = sm;                   // [128][WPAD], k-major: Wt[k*WPAD + c] = W[c][k]
    float* Xs = sm + 128 * WPAD;      // [64][XPAD]
    int tid = threadIdx.x;

    for (int i = tid; i < 128 * 128; i += 256) {
        int c = i >> 7, k = i & 127;
        Wt[k * WPAD + c] = W[i];
    }
    int rb = blockIdx.x * GEMM_BR;
    for (int i = tid; i < GEMM_BR * 128; i += 256) {
        int r = i >> 7, k = i & 127;
        int gr = rb + r;
        Xs[r * XPAD + k] = (gr < R) ? X[(size_t)gr * HD + k] : 0.f;
    }
    __syncthreads();

    int tx = tid & 15, ty = tid >> 4;
    int r0 = ty * 4;
    int c0 = tx * 8;
    ull acc[4][4];
    #pragma unroll
    for (int i = 0; i < 4; i++)
        #pragma unroll
        for (int j = 0; j < 4; j++) acc[i][j] = 0ull;

    #pragma unroll 2
    for (int k = 0; k < 128; k++) {
        ull wv[4];
        #pragma unroll
        for (int jp = 0; jp < 4; jp++)
            wv[jp] = *reinterpret_cast<const ull*>(&Wt[k * WPAD + c0 + 2 * jp]);
        #pragma unroll
        for (int i = 0; i < 4; i++) {
            float xs = Xs[(r0 + i) * XPAD + k];
            ull xx;
            PACK2(xx, xs);
            #pragma unroll
            for (int jp = 0; jp < 4; jp++)
                FFMA2(acc[i][jp], xx, wv[jp], acc[i][jp]);
        }
    }

    if (!do_ln) {
        #pragma unroll
        for (int i = 0; i < 4; i++) {
            int gr = rb + r0 + i;
            if (gr >= R) continue;
            float v[8];
            #pragma unroll
            for (int jp = 0; jp < 4; jp++) UNPACK2(v[2 * jp], v[2 * jp + 1], acc[i][jp]);
            float4 o0 = make_float4(fmaxf(v[0], 0.f), fmaxf(v[1], 0.f),
                                    fmaxf(v[2], 0.f), fmaxf(v[3], 0.f));
            float4 o1 = make_float4(fmaxf(v[4], 0.f), fmaxf(v[5], 0.f),
                                    fmaxf(v[6], 0.f), fmaxf(v[7], 0.f));
            float4* op = reinterpret_cast<float4*>(out + (size_t)gr * HD + c0);
            op[0] = o0;
            op[1] = o1;
        }
    } else {
        float gv[8], bv[8];
        {
            float4 g0 = __ldg(reinterpret_cast<const float4*>(gw + c0));
            float4 g1 = __ldg(reinterpret_cast<const float4*>(gw + c0) + 1);
            float4 b0 = __ldg(reinterpret_cast<const float4*>(bw + c0));
            float4 b1 = __ldg(reinterpret_cast<const float4*>(bw + c0) + 1);
            gv[0] = g0.x; gv[1] = g0.y; gv[2] = g0.z; gv[3] = g0.w;
            gv[4] = g1.x; gv[5] = g1.y; gv[6] = g1.z; gv[7] = g1.w;
            bv[0] = b0.x; bv[1] = b0.y; bv[2] = b0.z; bv[3] = b0.w;
            bv[4] = b1.x; bv[5] = b1.y; bv[6] = b1.z; bv[7] = b1.w;
        }
        const float a = 0.7f, oma = 0.3f;
        #pragma unroll
        for (int i = 0; i < 4; i++) {
            int gr = rb + r0 + i;
            bool ok = (gr < R);
            float v[8], e[8];
            #pragma unroll
            for (int jp = 0; jp < 4; jp++) UNPACK2(v[2 * jp], v[2 * jp + 1], acc[i][jp]);
            if (ok) {
                const float4* ep = reinterpret_cast<const float4*>(emb + (size_t)gr * HD + c0);
                float4 e0 = __ldg(ep), e1 = __ldg(ep + 1);
                e[0] = e0.x; e[1] = e0.y; e[2] = e0.z; e[3] = e0.w;
                e[4] = e1.x; e[5] = e1.y; e[6] = e1.z; e[7] = e1.w;
            } else {
                #pragma unroll
                for (int j = 0; j < 8; j++) e[j] = 0.f;
            }
            float x[8], s = 0.f, sq = 0.f;
            #pragma unroll
            for (int j = 0; j < 8; j++) {
                x[j] = oma * e[j] + a * fmaxf(v[j], 0.f);
                s += x[j];
                sq = fmaf(x[j], x[j], sq);
            }
            #pragma unroll
            for (int o = 8; o; o >>= 1) {
                s  += __shfl_xor_sync(0xFFFFFFFFu, s, o);
                sq += __shfl_xor_sync(0xFFFFFFFFu, sq, o);
            }
            float mu  = s * (1.0f / 128.0f);
            float var = sq * (1.0f / 128.0f) - mu * mu;
            float inv = rsqrtf(var + 1e-5f);
            if (ok) {
                float o[8];
                #pragma unroll
                for (int j = 0; j < 8; j++)
                    o[j] = (x[j] - mu) * inv * gv[j] + bv[j] + e[j];
                float4* op = reinterpret_cast<float4*>(out + (size_t)gr * HD + c0);
                op[0] = make_float4(o[0], o[1], o[2], o[3]);
                op[1] = make_float4(o[4], o[5], o[6], o[7]);
            }
        }
    }
}

// ---------------------------------------------------------------------------
// head: logits = relu(doc @ mlpW^T + mlpb) @ clfW^T + clfb   (f32x2 packed)
// ---------------------------------------------------------------------------
#define HPAD 130
__global__ void k_head(const float* __restrict__ doc, const float* __restrict__ mlpW,
                       const float* __restrict__ mlpb, const float* __restrict__ clfW,
                       const float* __restrict__ clfb, float* __restrict__ out) {
    extern __shared__ float sm[];
    float* Ws = sm;                       // [128][130]
    float* xs = Ws + 128 * HPAD;          // [128]
    float* mb = xs + 128;
    float* c0 = mb + 128;
    float* c1 = c0 + 128;
    __shared__ float red0[4], red1[4];

    int tid = threadIdx.x;
    for (int i = tid; i < 128 * 128; i += 128) {
        int r = i >> 7, k = i & 127;
        Ws[r * HPAD + k] = mlpW[i];
    }
    mb[tid] = mlpb[tid];
    c0[tid] = clfW[tid];
    c1[tid] = clfW[128 + tid];
    float cb0 = clfb[0], cb1 = clfb[1];
    __syncthreads();

    int lane = tid & 31, wid = tid >> 5;
    const ull* wrow = reinterpret_cast<const ull*>(&Ws[tid * HPAD]);
    for (int d = blockIdx.x; d < N_DOCS; d += gridDim.x) {
        xs[tid] = doc[(size_t)d * HD + tid];
        __syncthreads();
        ull acc2 = 0ull;
        const ull* x2 = reinterpret_cast<const ull*>(xs);
        #pragma unroll 8
        for (int kp = 0; kp < 64; kp++)
            FFMA2(acc2, x2[kp], wrow[kp], acc2);
        float alo, ahi;
        UNPACK2(alo, ahi, acc2);
        float h = fmaxf(alo + ahi + mb[tid], 0.f);
        float p0 = h * c0[tid];
        float p1 = h * c1[tid];
        #pragma unroll
        for (int o = 16; o; o >>= 1) {
            p0 += __shfl_down_sync(0xFFFFFFFFu, p0, o);
            p1 += __shfl_down_sync(0xFFFFFFFFu, p1, o);
        }
        if (lane == 0) { red0[wid] = p0; red1[wid] = p1; }
        __syncthreads();
        if (tid == 0) out[(size_t)d * 2]     = red0[0] + red0[1] + red0[2] + red0[3] + cb0;
        if (tid == 1) out[(size_t)d * 2 + 1] = red1[0] + red1[1] + red1[2] + red1[3] + cb1;
        __syncthreads();
    }
}

// ---------------------------------------------------------------------------
extern "C" void kernel_launch(void* const* d_in, const int* in_sizes, int n_in,
                              void* d_out, int out_size) {
    const int*   A_row  = (const int*)  d_in[0];
    const int*   A_col  = (const int*)  d_in[1];
    const float* A_val  = (const float*)d_in[2];
    const int*   X_row  = (const int*)  d_in[3];
    const int*   X_col  = (const int*)  d_in[4];
    const float* X_val  = (const float*)d_in[5];
    const float* emb_W  = (const float*)d_in[6];
    const float* lin1_W = (const float*)d_in[7];
    const float* lin2_W = (const float*)d_in[8];
    const float* norm_g = (const float*)d_in[9];
    const float* norm_b = (const float*)d_in[10];
    const float* mlp_W  = (const float*)d_in[11];
    const float* mlp_b  = (const float*)d_in[12];
    const float* clf_W  = (const float*)d_in[13];
    const float* clf_b  = (const float*)d_in[14];
    float* out = (float*)d_out;

    int E   = in_sizes[0];
    int NNZ = in_sizes[3];

    void *pb1, *pb2, *pdoc, *pAed, *pXed, *pArp, *pAwp, *pAcnt, *pXrp, *pXwp, *pXcnt;
    cudaGetSymbolAddress(&pb1, g_buf1);
    cudaGetSymbolAddress(&pb2, g_buf2);
    cudaGetSymbolAddress(&pdoc, g_doc);
    cudaGetSymbolAddress(&pAed, g_Aed);
    cudaGetSymbolAddress(&pXed, g_Xed);
    cudaGetSymbolAddress(&pArp, g_Arp);
    cudaGetSymbolAddress(&pAwp, g_Awp);
    cudaGetSymbolAddress(&pAcnt, g_Acnt);
    cudaGetSymbolAddress(&pXrp, g_Xrp);
    cudaGetSymbolAddress(&pXwp, g_Xwp);
    cudaGetSymbolAddress(&pXcnt, g_Xcnt);
    float* b1 = (float*)pb1;
    float* b2 = (float*)pb2;
    float* bd = (float*)pdoc;
    int2* Aed = (int2*)pAed;
    int2* Xed = (int2*)pXed;
    int *Arp = (int*)pArp, *Awp = (int*)pAwp, *Acnt = (int*)pAcnt;
    int *Xrp = (int*)pXrp, *Xwp = (int*)pXwp, *Xcnt = (int*)pXcnt;

    const int gemm_smem = (128 * WPAD + GEMM_BR * XPAD) * sizeof(float);  // ~99.6 KB
    const int head_smem = (128 * HPAD + 4 * 128) * sizeof(float);         // ~68.6 KB
    cudaFuncSetAttribute(k_gemm_fused, cudaFuncAttributeMaxDynamicSharedMemorySize, gemm_smem);
    cudaFuncSetAttribute(k_head,       cudaFuncAttributeMaxDynamicSharedMemorySize, head_smem);

    const int eg = (E + 255) / 256;
    const int xg = (NNZ + 255) / 256;
    const int spmmA_grid = (V_WORDS * 32 + 255) / 256;
    const int spmmX_grid = (N_DOCS * 32 + 255) / 256;
    const int gemm_grid  = (V_WORDS + GEMM_BR - 1) / GEMM_BR;

    // --- Build CSR for A (used twice) ---
    k_zero_int<<<(V_WORDS + 255) / 256, 256>>>(Acnt, V_WORDS);
    k_hist<<<eg, 256>>>(A_row, Acnt, E);
    k_scan<<<1, 1024>>>(Acnt, Arp, Awp, V_WORDS);
    k_scatter<<<eg, 256>>>(A_row, A_col, A_val, Awp, Aed, E);

    // --- Build CSR for X ---
    k_zero_int<<<(N_DOCS + 255) / 256, 256>>>(Xcnt, N_DOCS);
    k_hist<<<xg, 256>>>(X_row, Xcnt, NNZ);
    k_scan<<<1, 1024>>>(Xcnt, Xrp, Xwp, N_DOCS);
    k_scatter<<<xg, 256>>>(X_row, X_col, X_val, Xwp, Xed, NNZ);

    // 1) b1 = A @ emb_W
    k_spmm_csr<<<spmmA_grid, 256>>>(Arp, Aed, emb_W, b1, V_WORDS);
    // 2) b2 = relu(b1 @ lin1^T)
    k_gemm_fused<<<gemm_grid, 256, gemm_smem>>>(b1, lin1_W, b2, V_WORDS, 0,
                                                nullptr, nullptr, nullptr);
    // 3) b1 = A @ b2
    k_spmm_csr<<<spmmA_grid, 256>>>(Arp, Aed, b2, b1, V_WORDS);
    // 4) b2 = LN(0.3*emb + 0.7*relu(b1 @ lin2^T))*g + b + emb  (fused epilogue)
    k_gemm_fused<<<gemm_grid, 256, gemm_smem>>>(b1, lin2_W, b2, V_WORDS, 1,
                                                emb_W, norm_g, norm_b);
    // 5) doc = X @ b2
    k_spmm_csr<<<spmmX_grid, 256>>>(Xrp, Xed, b2, bd, N_DOCS);
    // 6) logits
    k_head<<<2000, 128, head_smem>>>(bd, mlp_W, mlp_b, clf_W, clf_b, out);
}